// round 13
// baseline (speedup 1.0000x reference)
#include <cuda_runtime.h>

// Problem constants (fixed by the dataset: pcd [8, 4096, 3] fp32, k = 5)
#define NB 8
#define NPTS 4096
#define KNN 5
#define NBKT 512
#define QTPB 128
#define INITW 384

typedef unsigned long long u64;

// Scratch (allocation-free rule -> __device__ globals)
__device__ float4 g_pts[NB * NPTS];       // z-bucket-sorted: x, y, z, |p|^2
__device__ int    g_orig[NB * NPTS];      // original index per sorted slot
__device__ int    g_bst[NB * (NBKT + 1)]; // bucket start offsets (exclusive scan)
__device__ float2 g_zinfo[NB];            // (zmin, bucket width)
__device__ float  g_partial[NB * 16];     // per-psum-CTA trace partial sums

// --------------------------------------------------------------------------
// K1 (fused build): per batch (1 CTA, 1024 thr): z min/max -> 512-bucket
// histogram -> exclusive scan -> scatter into bucket-sorted arrays.
// --------------------------------------------------------------------------
__global__ __launch_bounds__(1024) void build_kernel(const float* __restrict__ pcd)
{
    __shared__ float swmin[32], swmax[32];
    __shared__ int   scnt[NBKT];
    __shared__ int   scur[NBKT];
    __shared__ int   swsum[16];
    __shared__ float szi[2];

    const int b = blockIdx.x;
    const float* base = pcd + (size_t)b * NPTS * 3;
    const int tid = threadIdx.x;

    float zmn = 1e30f, zmx = -1e30f;
    for (int i = tid; i < NPTS; i += 1024) {
        float z = base[i * 3 + 2];
        zmn = fminf(zmn, z); zmx = fmaxf(zmx, z);
    }
#pragma unroll
    for (int off = 16; off; off >>= 1) {
        zmn = fminf(zmn, __shfl_xor_sync(0xffffffffu, zmn, off));
        zmx = fmaxf(zmx, __shfl_xor_sync(0xffffffffu, zmx, off));
    }
    if ((tid & 31) == 0) { swmin[tid >> 5] = zmn; swmax[tid >> 5] = zmx; }
    __syncthreads();
    if (tid == 0) {
        float a = swmin[0], c = swmax[0];
        for (int w = 1; w < 32; w++) { a = fminf(a, swmin[w]); c = fmaxf(c, swmax[w]); }
        a -= 1e-4f; c += 1e-4f;
        szi[0] = a; szi[1] = (c - a) / (float)NBKT;
        g_zinfo[b] = make_float2(a, (c - a) / (float)NBKT);
    }
    for (int i = tid; i < NBKT; i += 1024) scnt[i] = 0;
    __syncthreads();

    const float zm = szi[0];
    const float inv = 1.0f / szi[1];

    for (int i = tid; i < NPTS; i += 1024) {
        float z = base[i * 3 + 2];
        int bk = (int)((z - zm) * inv);
        bk = min(NBKT - 1, max(0, bk));
        atomicAdd(&scnt[bk], 1);
    }
    __syncthreads();

    // Exclusive scan of 512 counts (warps 0-15 fully active for tid<512).
    int v = 0, incl = 0;
    if (tid < NBKT) {
        v = scnt[tid];
        incl = v;
#pragma unroll
        for (int off = 1; off < 32; off <<= 1) {
            int n = __shfl_up_sync(0xffffffffu, incl, off);
            if ((tid & 31) >= off) incl += n;
        }
        if ((tid & 31) == 31) swsum[tid >> 5] = incl;
    }
    __syncthreads();
    if (tid < 16) {
        int wv = swsum[tid];
        int wi = wv;
#pragma unroll
        for (int off = 1; off < 16; off <<= 1) {
            int n = __shfl_up_sync(0x0000ffffu, wi, off);
            if (tid >= off) wi += n;
        }
        swsum[tid] = wi - wv;
    }
    __syncthreads();
    if (tid < NBKT) {
        int ex = incl - v + swsum[tid >> 5];
        scur[tid] = ex;
        g_bst[b * (NBKT + 1) + tid] = ex;
        if (tid == 0) g_bst[b * (NBKT + 1) + NBKT] = NPTS;
    }
    __syncthreads();

    for (int i = tid; i < NPTS; i += 1024) {
        float x = base[i * 3 + 0], y = base[i * 3 + 1], z = base[i * 3 + 2];
        int bk = (int)((z - zm) * inv);
        bk = min(NBKT - 1, max(0, bk));
        int pos = atomicAdd(&scur[bk], 1);
        g_pts[b * NPTS + pos] = make_float4(x, y, z, fmaf(x, x, fmaf(y, y, z * z)));
        g_orig[b * NPTS + pos] = i;
    }
}

// --------------------------------------------------------------------------
// K2 (query): warp-shared z-sweep exact kNN + covariance trace.
// cand = (bits(max(d2,0)) << 32) | orig  ->  u64 '<' == top_k order exactly.
// Warp scans a shared window [lo,hi]; per-lane stop when both bucket-edge z
// bounds (conservative) exceed its 5th distance; warp extends while any lane
// needs more. Over-scan is harmless; bounds never under-scan.
// --------------------------------------------------------------------------
__global__ __launch_bounds__(QTPB) void query_kernel(
    const float* __restrict__ pcd, float* __restrict__ out)
{
    extern __shared__ char smem[];
    float4* sp  = (float4*)smem;                               // 64 KB
    int*    sor = (int*)(smem + NPTS * 16);                    // 16 KB
    int*    sbs = (int*)(smem + NPTS * 16 + NPTS * 4);         // 2052 B

    const int b  = blockIdx.x >> 5;          // 32 CTAs per batch
    const int cb = (blockIdx.x & 31) * QTPB; // CTA's slot base within batch
    const int tid = threadIdx.x;

    for (int i = tid; i < NPTS; i += QTPB) {
        sp[i]  = g_pts[b * NPTS + i];
        sor[i] = g_orig[b * NPTS + i];
    }
    for (int i = tid; i <= NBKT; i += QTPB) sbs[i] = g_bst[b * (NBKT + 1) + i];
    __syncthreads();

    const float2 zi = g_zinfo[b];
    const float zmn = zi.x, wd = zi.y;

    const int t = cb + tid;                  // this thread's sorted slot
    const float4 q = sp[t];
    const float nx = -2.0f * q.x, ny = -2.0f * q.y, nz = -2.0f * q.z;
    const float q2 = q.w, qz = q.z;

    u64 h0 = ~0ull, h1 = ~0ull, h2 = ~0ull, h3 = ~0ull, h4 = ~0ull;

#define PROC(PJ, OJ)                                                          \
    {                                                                         \
        float key = fmaxf(                                                    \
            fmaf((PJ).x, nx, fmaf((PJ).y, ny, fmaf((PJ).z, nz, (PJ).w + q2))),\
            0.0f);                                                            \
        u64 cand = ((u64)__float_as_uint(key) << 32) | (unsigned)(OJ);        \
        if (cand < h4) {                                                      \
            bool l0 = cand < h0, l1 = cand < h1, l2 = cand < h2, l3 = cand < h3; \
            h4 = l3 ? h3 : cand;                                              \
            if (l3) { h3 = l2 ? h2 : cand;                                    \
            if (l2) { h2 = l1 ? h1 : cand;                                    \
            if (l1) { h1 = l0 ? h0 : cand;                                    \
            if (l0) { h0 = cand; } } } }                                      \
        }                                                                     \
    }

    const int wb = t & ~31;                  // warp slot base (cb is 32-aligned)
    int lo = max(wb - INITW, 0);
    int hi = min(wb + 31 + INITW, NPTS - 1);

    // Phase A: fixed initial window, chunked broadcast loads.
    int s = lo;
    for (; s + 4 <= hi + 1; s += 4) {
        float4 p0 = sp[s], p1 = sp[s + 1], p2 = sp[s + 2], p3 = sp[s + 3];
        int o0 = sor[s], o1 = sor[s + 1], o2 = sor[s + 2], o3 = sor[s + 3];
        PROC(p0, o0); PROC(p1, o1); PROC(p2, o2); PROC(p3, o3);
    }
    for (; s <= hi; s++) { float4 p = sp[s]; PROC(p, sor[s]); }

    // Bucket pointers (warp-uniform; binary search once).
    int ub, db;
    {
        int a = 0, e = NBKT, tgt = min(hi + 1, NPTS - 1);
        while (e - a > 1) { int m = (a + e) >> 1; if (sbs[m] <= tgt) a = m; else e = m; }
        ub = a;
        a = 0; e = NBKT; tgt = max(lo - 1, 0);
        while (e - a > 1) { int m = (a + e) >> 1; if (sbs[m] <= tgt) a = m; else e = m; }
        db = a;
    }

    // Phase B: extend while any lane's bound is not yet proven.
    for (;;) {
        const float k5f = __uint_as_float((unsigned)(h4 >> 32)); // NaN until 5 found
        bool needUp = false, needDown = false;
        if (hi < NPTS - 1) {
            while (sbs[ub + 1] <= hi + 1) ub++;          // bucket of slot hi+1
            float dz = fmaxf(zmn + (float)ub * wd - 1e-4f - qz, 0.0f);
            needUp = !(dz * dz * 0.999f - 1e-7f > k5f);  // NaN-safe: stays true
        }
        if (lo > 0) {
            while (sbs[db] > lo - 1) db--;               // bucket of slot lo-1
            float dz = fmaxf(qz - (zmn + (float)(db + 1) * wd + 1e-4f), 0.0f);
            needDown = !(dz * dz * 0.999f - 1e-7f > k5f);
        }
        const bool anyU = __any_sync(0xffffffffu, needUp);
        const bool anyD = __any_sync(0xffffffffu, needDown);
        if (!anyU && !anyD) break;
        if (anyU) {
            int e = min(hi + 32, NPTS - 1);
            for (int j = hi + 1; j <= e; j++) { float4 p = sp[j]; PROC(p, sor[j]); }
            hi = e;
        }
        if (anyD) {
            int e = max(lo - 32, 0);
            for (int j = lo - 1; j >= e; j--) { float4 p = sp[j]; PROC(p, sor[j]); }
            lo = e;
        }
    }
#undef PROC

    // Gather the 5 neighbors by original index; reference numerics.
    const float* basep = pcd + (size_t)b * NPTS * 3;
    const unsigned id0 = (unsigned)h0, id1 = (unsigned)h1, id2 = (unsigned)h2,
                   id3 = (unsigned)h3, id4 = (unsigned)h4;
    float px[KNN], py[KNN], pz[KNN];
    px[0] = basep[id0 * 3 + 0]; py[0] = basep[id0 * 3 + 1]; pz[0] = basep[id0 * 3 + 2];
    px[1] = basep[id1 * 3 + 0]; py[1] = basep[id1 * 3 + 1]; pz[1] = basep[id1 * 3 + 2];
    px[2] = basep[id2 * 3 + 0]; py[2] = basep[id2 * 3 + 1]; pz[2] = basep[id2 * 3 + 2];
    px[3] = basep[id3 * 3 + 0]; py[3] = basep[id3 * 3 + 1]; pz[3] = basep[id3 * 3 + 2];
    px[4] = basep[id4 * 3 + 0]; py[4] = basep[id4 * 3 + 1]; pz[4] = basep[id4 * 3 + 2];

    const float inv_k = 1.0f / (float)KNN;
    float mx = (px[0] + px[1] + px[2] + px[3] + px[4]) * inv_k;
    float my = (py[0] + py[1] + py[2] + py[3] + py[4]) * inv_k;
    float mz = (pz[0] + pz[1] + pz[2] + pz[3] + pz[4]) * inv_k;

    float tr = 0.0f;
#pragma unroll
    for (int c = 0; c < KNN; c++) {
        float dx = px[c] - mx, dy = py[c] - my, dz = pz[c] - mz;
        tr = fmaf(dx, dx, fmaf(dy, dy, fmaf(dz, dz, tr)));
    }
    tr *= 1.0f / (float)(KNN - 1);
    out[b * NPTS + sor[t]] = tr;
}

// --------------------------------------------------------------------------
// K3: deterministic per-CTA partial sums of traces (original index order).
// --------------------------------------------------------------------------
__global__ __launch_bounds__(256) void psum_kernel(const float* __restrict__ out)
{
    __shared__ float warp_sums[8];
    const int t = blockIdx.x * 256 + threadIdx.x;
    float s = out[t];
#pragma unroll
    for (int off = 16; off > 0; off >>= 1)
        s += __shfl_down_sync(0xffffffffu, s, off);
    if ((threadIdx.x & 31) == 0) warp_sums[threadIdx.x >> 5] = s;
    __syncthreads();
    if (threadIdx.x < 32) {
        float v = (threadIdx.x < 8) ? warp_sums[threadIdx.x] : 0.0f;
#pragma unroll
        for (int off = 4; off > 0; off >>= 1)
            v += __shfl_down_sync(0xffffffffu, v, off);
        if (threadIdx.x == 0) g_partial[blockIdx.x] = v;
    }
}

// --------------------------------------------------------------------------
// K4: normalize. 4 CTAs per batch; each redundantly sums its batch's 16
// partials with a fixed-order tree (deterministic) and scales its quarter.
// --------------------------------------------------------------------------
__global__ __launch_bounds__(256) void finalize_kernel(float* __restrict__ out)
{
    __shared__ float s_inv;
    const int b = blockIdx.x >> 2;
    const int quarter = blockIdx.x & 3;

    if (threadIdx.x < 32) {
        float v = (threadIdx.x < 16) ? g_partial[b * 16 + threadIdx.x] : 0.0f;
#pragma unroll
        for (int off = 8; off > 0; off >>= 1)
            v += __shfl_down_sync(0xffffffffu, v, off);
        if (threadIdx.x == 0) s_inv = 1.0f / (v + 1e-8f);
    }
    __syncthreads();

    const float inv = s_inv;
    float* o = out + (size_t)b * NPTS + quarter * (NPTS / 4);
#pragma unroll
    for (int i = 0; i < (NPTS / 4) / 256; i++)
        o[i * 256 + threadIdx.x] *= inv;
}

extern "C" void kernel_launch(void* const* d_in, const int* in_sizes, int n_in,
                              void* d_out, int out_size)
{
    const float* pcd = (const float*)d_in[0];
    float* out = (float*)d_out;

    static bool attr_set = false;  // idempotent host-side attribute
    const int smemq = NPTS * 16 + NPTS * 4 + (NBKT + 1) * 4;   // ~84 KB
    if (!attr_set) {
        cudaFuncSetAttribute(query_kernel,
                             cudaFuncAttributeMaxDynamicSharedMemorySize, smemq);
        attr_set = true;
    }

    build_kernel<<<NB, 1024>>>(pcd);
    query_kernel<<<NB * 32, QTPB, smemq>>>(pcd, out);
    psum_kernel<<<(NB * NPTS) / 256, 256>>>(out);
    finalize_kernel<<<NB * 4, 256>>>(out);
}

// round 14
// speedup vs baseline: 1.8987x; 1.8987x over previous
#include <cuda_runtime.h>

// Problem constants (fixed by the dataset: pcd [8, 4096, 3] fp32, k = 5)
#define NB 8
#define NPTS 4096
#define KNN 5
#define GDIM 16
#define GC (GDIM * GDIM * GDIM)    // 4096 cells
#define QTPB 128

typedef unsigned long long u64;

// Scratch (allocation-free rule -> __device__ globals)
__device__ float4 g_pts[NB * NPTS];      // cell-sorted: x, y, z, |p|^2
__device__ int    g_orig[NB * NPTS];     // original index per sorted slot
__device__ int    g_bst[NB * (GC + 1)];  // cell start offsets (+ total)
__device__ float  g_bbox[NB][8];         // minx,miny,minz, invwx,invwy,invwz, wmin
__device__ float  g_partial[NB * 16];    // per-psum-CTA trace partial sums

// --------------------------------------------------------------------------
// K1 (fused build, 1 CTA per batch, 1024 thr): bbox -> 4096-cell histogram
// -> exclusive scan -> scatter into cell-sorted arrays.
// Cell formula must match the query kernel exactly (same ops, same clamps).
// --------------------------------------------------------------------------
__global__ __launch_bounds__(1024) void build_kernel(const float* __restrict__ pcd)
{
    __shared__ float sred[6][32];
    __shared__ float sbb[7];
    __shared__ int   scnt[GC];      // 16 KB
    __shared__ int   scur[GC];      // 16 KB
    __shared__ int   swsum[32];

    const int b = blockIdx.x;
    const float* base = pcd + (size_t)b * NPTS * 3;
    const int tid = threadIdx.x;
    const int lane = tid & 31, wid = tid >> 5;

    // --- bbox ---
    float mnx = 1e30f, mny = 1e30f, mnz = 1e30f;
    float mxx = -1e30f, mxy = -1e30f, mxz = -1e30f;
    for (int i = tid; i < NPTS; i += 1024) {
        float x = base[i * 3 + 0], y = base[i * 3 + 1], z = base[i * 3 + 2];
        mnx = fminf(mnx, x); mny = fminf(mny, y); mnz = fminf(mnz, z);
        mxx = fmaxf(mxx, x); mxy = fmaxf(mxy, y); mxz = fmaxf(mxz, z);
    }
#pragma unroll
    for (int off = 16; off; off >>= 1) {
        mnx = fminf(mnx, __shfl_xor_sync(0xffffffffu, mnx, off));
        mny = fminf(mny, __shfl_xor_sync(0xffffffffu, mny, off));
        mnz = fminf(mnz, __shfl_xor_sync(0xffffffffu, mnz, off));
        mxx = fmaxf(mxx, __shfl_xor_sync(0xffffffffu, mxx, off));
        mxy = fmaxf(mxy, __shfl_xor_sync(0xffffffffu, mxy, off));
        mxz = fmaxf(mxz, __shfl_xor_sync(0xffffffffu, mxz, off));
    }
    if (lane == 0) {
        sred[0][wid] = mnx; sred[1][wid] = mny; sred[2][wid] = mnz;
        sred[3][wid] = mxx; sred[4][wid] = mxy; sred[5][wid] = mxz;
    }
    __syncthreads();
    if (tid == 0) {
        float a0 = sred[0][0], a1 = sred[1][0], a2 = sred[2][0];
        float a3 = sred[3][0], a4 = sred[4][0], a5 = sred[5][0];
        for (int w = 1; w < 32; w++) {
            a0 = fminf(a0, sred[0][w]); a1 = fminf(a1, sred[1][w]); a2 = fminf(a2, sred[2][w]);
            a3 = fmaxf(a3, sred[3][w]); a4 = fmaxf(a4, sred[4][w]); a5 = fmaxf(a5, sred[5][w]);
        }
        float ex = (a3 - a0) + 1e-5f;
        float ey = (a4 - a1) + 1e-5f;
        float ez = (a5 - a2) + 1e-5f;
        sbb[0] = a0; sbb[1] = a1; sbb[2] = a2;
        sbb[3] = (float)GDIM / ex;
        sbb[4] = (float)GDIM / ey;
        sbb[5] = (float)GDIM / ez;
        sbb[6] = fminf(ex, fminf(ey, ez)) / (float)GDIM;   // wmin
        g_bbox[b][0] = sbb[0]; g_bbox[b][1] = sbb[1]; g_bbox[b][2] = sbb[2];
        g_bbox[b][3] = sbb[3]; g_bbox[b][4] = sbb[4]; g_bbox[b][5] = sbb[5];
        g_bbox[b][6] = sbb[6];
    }
    for (int i = tid; i < GC; i += 1024) scnt[i] = 0;
    __syncthreads();

    const float bx = sbb[0], by = sbb[1], bz = sbb[2];
    const float ix = sbb[3], iy = sbb[4], iz = sbb[5];

    // --- histogram ---
    for (int i = tid; i < NPTS; i += 1024) {
        float x = base[i * 3 + 0], y = base[i * 3 + 1], z = base[i * 3 + 2];
        int cx = min(GDIM - 1, max(0, (int)((x - bx) * ix)));
        int cy = min(GDIM - 1, max(0, (int)((y - by) * iy)));
        int cz = min(GDIM - 1, max(0, (int)((z - bz) * iz)));
        atomicAdd(&scnt[(cz * GDIM + cy) * GDIM + cx], 1);
    }
    __syncthreads();

    // --- exclusive scan of 4096 counts (4 cells per thread) ---
    const int c0 = tid * 4;
    int T = scnt[c0] + scnt[c0 + 1] + scnt[c0 + 2] + scnt[c0 + 3];
    int incl = T;
#pragma unroll
    for (int off = 1; off < 32; off <<= 1) {
        int n = __shfl_up_sync(0xffffffffu, incl, off);
        if (lane >= off) incl += n;
    }
    if (lane == 31) swsum[wid] = incl;
    __syncthreads();
    if (wid == 0) {
        int v = swsum[lane];
        int iv = v;
#pragma unroll
        for (int off = 1; off < 32; off <<= 1) {
            int n = __shfl_up_sync(0xffffffffu, iv, off);
            if (lane >= off) iv += n;
        }
        swsum[lane] = iv - v;
    }
    __syncthreads();
    {
        int run = swsum[wid] + (incl - T);
#pragma unroll
        for (int i = 0; i < 4; i++) {
            int c = scnt[c0 + i];
            scur[c0 + i] = run;
            g_bst[b * (GC + 1) + c0 + i] = run;
            run += c;
        }
        if (tid == 0) g_bst[b * (GC + 1) + GC] = NPTS;
    }
    __syncthreads();

    // --- scatter ---
    for (int i = tid; i < NPTS; i += 1024) {
        float x = base[i * 3 + 0], y = base[i * 3 + 1], z = base[i * 3 + 2];
        int cx = min(GDIM - 1, max(0, (int)((x - bx) * ix)));
        int cy = min(GDIM - 1, max(0, (int)((y - by) * iy)));
        int cz = min(GDIM - 1, max(0, (int)((z - bz) * iz)));
        int pos = atomicAdd(&scur[(cz * GDIM + cy) * GDIM + cx], 1);
        g_pts[b * NPTS + pos] = make_float4(x, y, z, fmaf(x, x, fmaf(y, y, z * z)));
        g_orig[b * NPTS + pos] = i;
    }
}

// --------------------------------------------------------------------------
// K2 (query): expanding-shell exact kNN, all data smem-resident; faces are
// scanned as x-contiguous runs (one [start,end) interval per face row).
// cand = (bits(max(d2,0)) << 32) | orig  ->  u64 '<' == top_k order exactly
// (smaller distance first, lowest index on ties).
// Stop after shell s: unscanned cells are >= s cells away on some axis ->
// distance >= s*wmin; margin covers fp error. NaN (< 5 found) keeps going.
// --------------------------------------------------------------------------
__global__ __launch_bounds__(QTPB) void query_kernel(
    const float* __restrict__ pcd, float* __restrict__ out)
{
    extern __shared__ char smem[];
    float4* sp  = (float4*)smem;                               // 64 KB
    int*    sor = (int*)(smem + NPTS * 16);                    // 16 KB
    int*    sst = (int*)(smem + NPTS * 16 + NPTS * 4);         // (GC+1)*4 B

    const int b  = blockIdx.x >> 5;          // 32 CTAs per batch
    const int t  = (blockIdx.x & 31) * QTPB + threadIdx.x;  // sorted slot in batch

    for (int i = threadIdx.x; i < NPTS; i += QTPB) {
        sp[i]  = g_pts[b * NPTS + i];
        sor[i] = g_orig[b * NPTS + i];
    }
    for (int i = threadIdx.x; i <= GC; i += QTPB)
        sst[i] = g_bst[b * (GC + 1) + i];
    __syncthreads();

    const float bx = g_bbox[b][0], by = g_bbox[b][1], bz = g_bbox[b][2];
    const float ix = g_bbox[b][3], iy = g_bbox[b][4], iz = g_bbox[b][5];
    const float wmin = g_bbox[b][6];

    const float4 q = sp[t];
    const float nx = -2.0f * q.x, ny = -2.0f * q.y, nz = -2.0f * q.z;
    const float q2 = q.w;

    const int cx = min(GDIM - 1, max(0, (int)((q.x - bx) * ix)));
    const int cy = min(GDIM - 1, max(0, (int)((q.y - by) * iy)));
    const int cz = min(GDIM - 1, max(0, (int)((q.z - bz) * iz)));

    u64 h0 = ~0ull, h1 = ~0ull, h2 = ~0ull, h3 = ~0ull, h4 = ~0ull;

    // One x-contiguous run of cells [X0..X1] at fixed (Y,Z).
#define PROCR(X0, X1, Y, Z)                                                   \
    {                                                                         \
        const int cid0 = ((Z) * GDIM + (Y)) * GDIM + (X0);                    \
        const int cs = sst[cid0];                                             \
        const int ce = sst[cid0 + ((X1) - (X0)) + 1];                         \
        for (int i = cs; i < ce; i++) {                                       \
            float4 p = sp[i];                                                 \
            float key = fmaxf(                                                \
                fmaf(p.x, nx, fmaf(p.y, ny, fmaf(p.z, nz, p.w + q2))), 0.0f); \
            u64 cand = ((u64)__float_as_uint(key) << 32) | (unsigned)sor[i];  \
            if (cand < h4) {                                                  \
                bool l0 = cand < h0, l1 = cand < h1, l2 = cand < h2, l3 = cand < h3; \
                h4 = l3 ? h3 : cand;                                          \
                if (l3) { h3 = l2 ? h2 : cand;                                \
                if (l2) { h2 = l1 ? h1 : cand;                                \
                if (l1) { h1 = l0 ? h0 : cand;                                \
                if (l0) { h0 = cand; } } } }                                  \
            }                                                                 \
        }                                                                     \
    }

    for (int s = 0; s < GDIM; s++) {
        if (s == 0) {
            PROCR(cx, cx, cy, cz);
        } else {
            const int x0 = max(cx - s, 0), x1 = min(cx + s, GDIM - 1);
            const int y0 = max(cy - s, 0), y1 = min(cy + s, GDIM - 1);
            const int zi0 = max(cz - s + 1, 0), zi1 = min(cz + s - 1, GDIM - 1);
            const int yi0 = max(cy - s + 1, 0), yi1 = min(cy + s - 1, GDIM - 1);
            // z faces: |dz| = s, y/x full
            if (cz - s >= 0)
                for (int y = y0; y <= y1; y++) PROCR(x0, x1, y, cz - s);
            if (cz + s < GDIM)
                for (int y = y0; y <= y1; y++) PROCR(x0, x1, y, cz + s);
            // y faces: |dy| = s, z inner, x full
            if (cy - s >= 0)
                for (int z = zi0; z <= zi1; z++) PROCR(x0, x1, cy - s, z);
            if (cy + s < GDIM)
                for (int z = zi0; z <= zi1; z++) PROCR(x0, x1, cy + s, z);
            // x faces: |dx| = s, z inner, y inner
            if (cx - s >= 0)
                for (int z = zi0; z <= zi1; z++)
                    for (int y = yi0; y <= yi1; y++) PROCR(cx - s, cx - s, y, z);
            if (cx + s < GDIM)
                for (int z = zi0; z <= zi1; z++)
                    for (int y = yi0; y <= yi1; y++) PROCR(cx + s, cx + s, y, z);
        }
        const float k5 = __uint_as_float((unsigned)(h4 >> 32));
        const float lim = (float)s * wmin;
        if (k5 <= lim * lim * 0.999f - 1e-4f) break;
    }
#undef PROCR

    // Gather the 5 neighbors by original index; reference numerics.
    const float* basep = pcd + (size_t)b * NPTS * 3;
    const unsigned id0 = (unsigned)h0, id1 = (unsigned)h1, id2 = (unsigned)h2,
                   id3 = (unsigned)h3, id4 = (unsigned)h4;
    float px[KNN], py[KNN], pz[KNN];
    px[0] = basep[id0 * 3 + 0]; py[0] = basep[id0 * 3 + 1]; pz[0] = basep[id0 * 3 + 2];
    px[1] = basep[id1 * 3 + 0]; py[1] = basep[id1 * 3 + 1]; pz[1] = basep[id1 * 3 + 2];
    px[2] = basep[id2 * 3 + 0]; py[2] = basep[id2 * 3 + 1]; pz[2] = basep[id2 * 3 + 2];
    px[3] = basep[id3 * 3 + 0]; py[3] = basep[id3 * 3 + 1]; pz[3] = basep[id3 * 3 + 2];
    px[4] = basep[id4 * 3 + 0]; py[4] = basep[id4 * 3 + 1]; pz[4] = basep[id4 * 3 + 2];

    const float inv_k = 1.0f / (float)KNN;
    float mx = (px[0] + px[1] + px[2] + px[3] + px[4]) * inv_k;
    float my = (py[0] + py[1] + py[2] + py[3] + py[4]) * inv_k;
    float mz = (pz[0] + pz[1] + pz[2] + pz[3] + pz[4]) * inv_k;

    float tr = 0.0f;
#pragma unroll
    for (int c = 0; c < KNN; c++) {
        float dx = px[c] - mx, dy = py[c] - my, dz = pz[c] - mz;
        tr = fmaf(dx, dx, fmaf(dy, dy, fmaf(dz, dz, tr)));
    }
    tr *= 1.0f / (float)(KNN - 1);
    out[b * NPTS + sor[t]] = tr;
}

// --------------------------------------------------------------------------
// K3: deterministic per-CTA partial sums of traces (original index order).
// --------------------------------------------------------------------------
__global__ __launch_bounds__(256) void psum_kernel(const float* __restrict__ out)
{
    __shared__ float warp_sums[8];
    const int t = blockIdx.x * 256 + threadIdx.x;
    float s = out[t];
#pragma unroll
    for (int off = 16; off > 0; off >>= 1)
        s += __shfl_down_sync(0xffffffffu, s, off);
    if ((threadIdx.x & 31) == 0) warp_sums[threadIdx.x >> 5] = s;
    __syncthreads();
    if (threadIdx.x < 32) {
        float v = (threadIdx.x < 8) ? warp_sums[threadIdx.x] : 0.0f;
#pragma unroll
        for (int off = 4; off > 0; off >>= 1)
            v += __shfl_down_sync(0xffffffffu, v, off);
        if (threadIdx.x == 0) g_partial[blockIdx.x] = v;
    }
}

// --------------------------------------------------------------------------
// K4: normalize. 4 CTAs per batch; each redundantly sums its batch's 16
// partials with a fixed-order tree (deterministic) and scales its quarter.
// --------------------------------------------------------------------------
__global__ __launch_bounds__(256) void finalize_kernel(float* __restrict__ out)
{
    __shared__ float s_inv;
    const int b = blockIdx.x >> 2;
    const int quarter = blockIdx.x & 3;

    if (threadIdx.x < 32) {
        float v = (threadIdx.x < 16) ? g_partial[b * 16 + threadIdx.x] : 0.0f;
#pragma unroll
        for (int off = 8; off > 0; off >>= 1)
            v += __shfl_down_sync(0xffffffffu, v, off);
        if (threadIdx.x == 0) s_inv = 1.0f / (v + 1e-8f);
    }
    __syncthreads();

    const float inv = s_inv;
    float* o = out + (size_t)b * NPTS + quarter * (NPTS / 4);
#pragma unroll
    for (int i = 0; i < (NPTS / 4) / 256; i++)
        o[i * 256 + threadIdx.x] *= inv;
}

extern "C" void kernel_launch(void* const* d_in, const int* in_sizes, int n_in,
                              void* d_out, int out_size)
{
    const float* pcd = (const float*)d_in[0];
    float* out = (float*)d_out;

    static bool attr_set = false;  // idempotent host-side attribute
    const int smemq = NPTS * 16 + NPTS * 4 + (GC + 1) * 4;   // ~96.4 KB
    if (!attr_set) {
        cudaFuncSetAttribute(query_kernel,
                             cudaFuncAttributeMaxDynamicSharedMemorySize, smemq);
        attr_set = true;
    }

    build_kernel<<<NB, 1024>>>(pcd);
    query_kernel<<<NB * 32, QTPB, smemq>>>(pcd, out);
    psum_kernel<<<(NB * NPTS) / 256, 256>>>(out);
    finalize_kernel<<<NB * 4, 256>>>(out);
}